// round 14
// baseline (speedup 1.0000x reference)
#include <cuda_runtime.h>
#include <cstdint>

#define ALPHA 26
#define TPB   256
#define WARPS (TPB / 32)                 // 8 warps per block
#define CHUNK_TOK    64                  // tokens per warp-chunk (2 per lane)
#define CHUNK_FLOATS (CHUNK_TOK * ALPHA) // 1664
#define CHUNK_BYTES  (CHUNK_FLOATS * 4)  // 6656 (16B multiple)
#define SEQ   8192
#define GRID  296                        // 2 blocks/SM * 148 SMs
#define TW    (GRID * WARPS)             // 2368 warp pipelines

__constant__ float c_rot[ALPHA * ALPHA]; // RAW rotor, row-major (normalization folded into x)

__device__ __forceinline__ uint32_t smem_u32(const void* p) {
    return (uint32_t)__cvta_generic_to_shared(p);
}
__device__ __forceinline__ void mbar_init(uint32_t mbar, uint32_t cnt) {
    asm volatile("mbarrier.init.shared.b64 [%0], %1;" :: "r"(mbar), "r"(cnt) : "memory");
}
__device__ __forceinline__ void mbar_expect_tx(uint32_t mbar, uint32_t bytes) {
    asm volatile("mbarrier.arrive.expect_tx.shared.b64 _, [%0], %1;"
                 :: "r"(mbar), "r"(bytes) : "memory");
}
__device__ __forceinline__ void mbar_wait(uint32_t mbar, uint32_t parity) {
    asm volatile(
        "{\n\t.reg .pred P;\n\t"
        "WAIT_%=:\n\t"
        "mbarrier.try_wait.parity.acquire.cta.shared::cta.b64 P, [%0], %1, 0x989680;\n\t"
        "@P bra.uni DONE_%=;\n\t"
        "bra.uni WAIT_%=;\n\t"
        "DONE_%=:\n\t}"
        :: "r"(mbar), "r"(parity) : "memory");
}
__device__ __forceinline__ void bulk_load(uint32_t sdst, const void* gsrc,
                                          uint32_t bytes, uint32_t mbar) {
    asm volatile(
        "cp.async.bulk.shared::cta.global.mbarrier::complete_tx::bytes [%0], [%1], %2, [%3];"
        :: "r"(sdst), "l"(gsrc), "r"(bytes), "r"(mbar) : "memory");
}
__device__ __forceinline__ void bulk_store(void* gdst, uint32_t ssrc, uint32_t bytes) {
    asm volatile("cp.async.bulk.global.shared::cta.bulk_group [%0], [%1], %2;"
                 :: "l"(gdst), "r"(ssrc), "r"(bytes) : "memory");
}
__device__ __forceinline__ void bulk_commit()    { asm volatile("cp.async.bulk.commit_group;" ::: "memory"); }
__device__ __forceinline__ void bulk_wait_read() { asm volatile("cp.async.bulk.wait_group.read 0;" ::: "memory"); }
__device__ __forceinline__ void bulk_wait_all()  { asm volatile("cp.async.bulk.wait_group 0;" ::: "memory"); }
__device__ __forceinline__ void fence_async()    { asm volatile("fence.proxy.async.shared::cta;" ::: "memory"); }

__global__ __launch_bounds__(TPB, 2)
void rotor_kernel(const float* __restrict__ x,
                  const float* __restrict__ rotor,
                  float* __restrict__ out, int nChunks)
{
    extern __shared__ __align__(128) float s_dyn[];   // WARPS * 2 * CHUNK_FLOATS
    __shared__ float s_inv[ALPHA];                    // 1/||rotor_row|| per row
    __shared__ __align__(8) unsigned long long s_mbar[WARPS * 2];

    const int tid  = threadIdx.x;
    const int wid  = tid >> 5;
    const int lane = tid & 31;

    // --- per-row inverse norms (cheap, once per persistent block) ---
    if (tid < ALPHA) {
        float ss = 0.f;
        #pragma unroll
        for (int j = 0; j < ALPHA; ++j) {
            float v = rotor[tid * ALPHA + j];
            ss = fmaf(v, v, ss);
        }
        s_inv[tid] = rsqrtf(ss);
    }
    if (tid < WARPS * 2) mbar_init(smem_u32(&s_mbar[tid]), 1);
    __syncthreads();   // s_inv + mbarrier init visible to all warps

    // per-warp resources
    float* __restrict__ wbuf = s_dyn + wid * 2 * CHUNK_FLOATS;
    const uint32_t wb  = smem_u32(wbuf);
    const uint32_t mbA = smem_u32(&s_mbar[wid * 2 + 0]);
    const uint32_t mbB = smem_u32(&s_mbar[wid * 2 + 1]);

    const int c0 = blockIdx.x * WARPS + wid;   // this warp's first chunk

    // --- prologue: prefetch first two chunks (lane 0 only) ---
    if (lane == 0) {
        if (c0 < nChunks) {
            mbar_expect_tx(mbA, CHUNK_BYTES);
            bulk_load(wb, x + (size_t)c0 * CHUNK_FLOATS, CHUNK_BYTES, mbA);
        }
        if (c0 + TW < nChunks) {
            mbar_expect_tx(mbB, CHUNK_BYTES);
            bulk_load(wb + CHUNK_BYTES, x + (size_t)(c0 + TW) * CHUNK_FLOATS,
                      CHUNK_BYTES, mbB);
        }
    }

    int k = 0;
    for (int c = c0; c < nChunks; c += TW, ++k) {
        const int b  = k & 1;
        const int ph = (k >> 1) & 1;
        mbar_wait(b ? mbB : mbA, ph);

        float* __restrict__ sb = wbuf + b * CHUNK_FLOATS;

        // --- two tokens per lane ---
        const int tok0 = c * CHUNK_TOK + lane;
        const int tok1 = tok0 + 32;
        const int shift0 = (tok0 & (SEQ - 1)) % ALPHA;
        const int shift1 = (tok1 & (SEQ - 1)) % ALPHA;
        const float* __restrict__ xr0 = sb + lane * ALPHA;
        const float* __restrict__ xr1 = sb + (lane + 32) * ALPHA;

        unsigned long long acc0[13], acc1[13];
        #pragma unroll
        for (int p = 0; p < 13; ++p) { acc0[p] = 0ull; acc1[p] = 0ull; }

        #pragma unroll
        for (int r = 0; r < ALPHA; ++r) {
            int i0 = r - shift0; i0 += (i0 >> 31) & ALPHA;
            int i1 = r - shift1; i1 += (i1 >> 31) & ALPHA;
            const float invr = s_inv[r];               // uniform smem broadcast
            float xs0 = xr0[i0] * invr;                // fold row normalization into x
            float xs1 = xr1[i1] * invr;
            unsigned long long xx0, xx1;
            asm("mov.b64 %0, {%1, %1};" : "=l"(xx0) : "f"(xs0));
            asm("mov.b64 %0, {%1, %1};" : "=l"(xx1) : "f"(xs1));

            // raw rotor row r from CONSTANT memory: 13 x 8B, compile-time offsets
            #pragma unroll
            for (int p = 0; p < 13; ++p) {
                float2 f = *(const float2*)(c_rot + r * ALPHA + 2 * p);
                unsigned long long bb;
                asm("mov.b64 %0, {%1, %2};" : "=l"(bb) : "f"(f.x), "f"(f.y));
                asm("fma.rn.f32x2 %0, %1, %2, %0;" : "+l"(acc0[p]) : "l"(bb), "l"(xx0));
                asm("fma.rn.f32x2 %0, %1, %2, %0;" : "+l"(acc1[p]) : "l"(bb), "l"(xx1));
            }
        }

        // --- softmax (no max-subtract: unit-norm rows, x ~ N(0,1), |logit| < ~7) ---
        float e0[ALPHA], e1[ALPHA];
        #pragma unroll
        for (int p = 0; p < 13; ++p) {
            float a, bvf, cvf, d;
            asm("mov.b64 {%0, %1}, %2;" : "=f"(a), "=f"(bvf) : "l"(acc0[p]));
            asm("mov.b64 {%0, %1}, %2;" : "=f"(cvf), "=f"(d) : "l"(acc1[p]));
            e0[2*p] = __expf(a);   e0[2*p+1] = __expf(bvf);
            e1[2*p] = __expf(cvf); e1[2*p+1] = __expf(d);
        }
        // tree sums (depth ~5)
        float t0[13], t1[13];
        #pragma unroll
        for (int p = 0; p < 13; ++p) { t0[p] = e0[2*p] + e0[2*p+1]; t1[p] = e1[2*p] + e1[2*p+1]; }
        float s0a = (t0[0] + t0[1]) + (t0[2] + t0[3]);
        float s0b = (t0[4] + t0[5]) + (t0[6] + t0[7]);
        float s0c = (t0[8] + t0[9]) + (t0[10] + t0[11]);
        float sm0 = (s0a + s0b) + (s0c + t0[12]);
        float s1a = (t1[0] + t1[1]) + (t1[2] + t1[3]);
        float s1b = (t1[4] + t1[5]) + (t1[6] + t1[7]);
        float s1c = (t1[8] + t1[9]) + (t1[10] + t1[11]);
        float sm1 = (s1a + s1b) + (s1c + t1[12]);

        const float in0 = __fdividef(1.0f, sm0);
        const float in1 = __fdividef(1.0f, sm1);
        unsigned long long iv0, iv1;
        asm("mov.b64 %0, {%1, %1};" : "=l"(iv0) : "f"(in0));
        asm("mov.b64 %0, {%1, %1};" : "=l"(iv1) : "f"(in1));

        // packed scale + 8B shared stores into own rows of sb
        unsigned long long* w0 = (unsigned long long*)(sb + lane * ALPHA);
        unsigned long long* w1 = (unsigned long long*)(sb + (lane + 32) * ALPHA);
        #pragma unroll
        for (int p = 0; p < 13; ++p) {
            unsigned long long p0, p1, r0, r1;
            asm("mov.b64 %0, {%1, %2};" : "=l"(p0) : "f"(e0[2*p]), "f"(e0[2*p+1]));
            asm("mov.b64 %0, {%1, %2};" : "=l"(p1) : "f"(e1[2*p]), "f"(e1[2*p+1]));
            asm("mul.rn.f32x2 %0, %1, %2;" : "=l"(r0) : "l"(p0), "l"(iv0));
            asm("mul.rn.f32x2 %0, %1, %2;" : "=l"(r1) : "l"(p1), "l"(iv1));
            w0[p] = r0;
            w1[p] = r1;
        }
        __syncwarp();                                // warp's STS all done

        if (lane == 0) {
            fence_async();                           // STS visible to async proxy
            bulk_store(out + (size_t)c * CHUNK_FLOATS, wb + b * CHUNK_BYTES, CHUNK_BYTES);
            bulk_commit();
            const int cn = c + 2 * TW;
            if (cn < nChunks) {
                bulk_wait_read();                    // this buffer's store reads drained
                mbar_expect_tx(b ? mbB : mbA, CHUNK_BYTES);
                bulk_load(wb + b * CHUNK_BYTES, x + (size_t)cn * CHUNK_FLOATS,
                          CHUNK_BYTES, b ? mbB : mbA);
            }
        }
        // lanes 1..31 run ahead to next chunk's mbar_wait (other buffer) — safe
    }

    if (lane == 0) bulk_wait_all();                  // gmem stores complete before exit
}

extern "C" void kernel_launch(void* const* d_in, const int* in_sizes, int n_in,
                              void* d_out, int out_size)
{
    const float* x     = (const float*)d_in[0];   // [128, 8192, 26] f32
    const float* rotor = (const float*)d_in[1];   // [26, 26] f32
    float* out         = (float*)d_out;

    const int total_tokens = out_size / ALPHA;    // 1,048,576
    const int nChunks = total_tokens / CHUNK_TOK; // 16384

    // raw rotor -> constant bank (single D2D memcpy node; graph-capturable)
    cudaMemcpyToSymbolAsync(c_rot, rotor, ALPHA * ALPHA * sizeof(float), 0,
                            cudaMemcpyDeviceToDevice, 0);

    const int dyn_smem = WARPS * 2 * CHUNK_BYTES; // 106496 B
    cudaFuncSetAttribute(rotor_kernel,
                         cudaFuncAttributeMaxDynamicSharedMemorySize, dyn_smem);

    rotor_kernel<<<GRID, TPB, dyn_smem>>>(x, rotor, out, nChunks);
}

// round 15
// speedup vs baseline: 1.0539x; 1.0539x over previous
#include <cuda_runtime.h>
#include <cuda.h>
#include <cstdint>
#include <dlfcn.h>

#define ALPHA 26
#define TPB   256
#define WARPS (TPB / 32)                 // 8 warps per block
#define CHUNK_TOK    64                  // tokens per warp-chunk (2 per lane)
#define CHUNK_FLOATS (CHUNK_TOK * ALPHA) // 1664
#define CHUNK_BYTES  (CHUNK_FLOATS * 4)  // 6656
#define SEQ   8192
#define NBATCH 128
#define GRID  296                        // 2 blocks/SM * 148 SMs
#define TW    (GRID * WARPS)             // 2368 warp pipelines

__device__ __forceinline__ uint32_t smem_u32(const void* p) {
    return (uint32_t)__cvta_generic_to_shared(p);
}
__device__ __forceinline__ void mbar_init(uint32_t mbar, uint32_t cnt) {
    asm volatile("mbarrier.init.shared.b64 [%0], %1;" :: "r"(mbar), "r"(cnt) : "memory");
}
__device__ __forceinline__ void mbar_expect_tx(uint32_t mbar, uint32_t bytes) {
    asm volatile("mbarrier.arrive.expect_tx.shared.b64 _, [%0], %1;"
                 :: "r"(mbar), "r"(bytes) : "memory");
}
__device__ __forceinline__ void mbar_wait(uint32_t mbar, uint32_t parity) {
    asm volatile(
        "{\n\t.reg .pred P;\n\t"
        "WAIT_%=:\n\t"
        "mbarrier.try_wait.parity.acquire.cta.shared::cta.b64 P, [%0], %1, 0x989680;\n\t"
        "@P bra.uni DONE_%=;\n\t"
        "bra.uni WAIT_%=;\n\t"
        "DONE_%=:\n\t}"
        :: "r"(mbar), "r"(parity) : "memory");
}
__device__ __forceinline__ void bulk_load(uint32_t sdst, const void* gsrc,
                                          uint32_t bytes, uint32_t mbar) {
    asm volatile(
        "cp.async.bulk.shared::cta.global.mbarrier::complete_tx::bytes [%0], [%1], %2, [%3];"
        :: "r"(sdst), "l"(gsrc), "r"(bytes), "r"(mbar) : "memory");
}
__device__ __forceinline__ void bulk_store(void* gdst, uint32_t ssrc, uint32_t bytes) {
    asm volatile("cp.async.bulk.global.shared::cta.bulk_group [%0], [%1], %2;"
                 :: "l"(gdst), "r"(ssrc), "r"(bytes) : "memory");
}
__device__ __forceinline__ void tmap_load_2d(uint32_t sdst, const void* tmap,
                                             int c0, int c1, uint32_t mbar) {
    asm volatile(
        "cp.async.bulk.tensor.2d.shared::cta.global.tile.mbarrier::complete_tx::bytes "
        "[%0], [%1, {%2, %3}], [%4];"
        :: "r"(sdst), "l"(tmap), "r"(c0), "r"(c1), "r"(mbar) : "memory");
}
__device__ __forceinline__ void tmap_store_2d(const void* tmap, int c0, int c1,
                                              uint32_t ssrc) {
    asm volatile(
        "cp.async.bulk.tensor.2d.global.shared::cta.tile.bulk_group [%0, {%1, %2}], [%3];"
        :: "l"(tmap), "r"(c0), "r"(c1), "r"(ssrc) : "memory");
}
__device__ __forceinline__ void bulk_commit()    { asm volatile("cp.async.bulk.commit_group;" ::: "memory"); }
__device__ __forceinline__ void bulk_wait_read() { asm volatile("cp.async.bulk.wait_group.read 0;" ::: "memory"); }
__device__ __forceinline__ void bulk_wait_all()  { asm volatile("cp.async.bulk.wait_group 0;" ::: "memory"); }
__device__ __forceinline__ void fence_async()    { asm volatile("fence.proxy.async.shared::cta;" ::: "memory"); }

// ======== common compute helpers ========
#define PACK_DUP(dst, v)  asm("mov.b64 %0, {%1, %1};" : "=l"(dst) : "f"(v))
#define PACK2(dst, a, b)  asm("mov.b64 %0, {%1, %2};" : "=l"(dst) : "f"(a), "f"(b))
#define UNPACK2(a, b, s)  asm("mov.b64 {%0, %1}, %2;" : "=f"(a), "=f"(b) : "l"(s))
#define FMA2(acc, b, x)   asm("fma.rn.f32x2 %0, %1, %2, %0;" : "+l"(acc) : "l"(b), "l"(x))
#define MUL2(d, a, b)     asm("mul.rn.f32x2 %0, %1, %2;" : "=l"(d) : "l"(a), "l"(b))

// full row FMA: 7 uniform loads from row pointer, 13 FMA2s into acc for one xx
__device__ __forceinline__ void row_fma2(const char* rowp,
                                         unsigned long long* acc0, unsigned long long xx0,
                                         unsigned long long* acc1, unsigned long long xx1) {
    #pragma unroll
    for (int cc = 0; cc < 6; ++cc) {
        float4 f = *(const float4*)(rowp + 16 * cc);
        unsigned long long b01, b23;
        PACK2(b01, f.x, f.y);
        PACK2(b23, f.z, f.w);
        FMA2(acc0[2*cc  ], b01, xx0);
        FMA2(acc0[2*cc+1], b23, xx0);
        FMA2(acc1[2*cc  ], b01, xx1);
        FMA2(acc1[2*cc+1], b23, xx1);
    }
    float2 f = *(const float2*)(rowp + 96);
    unsigned long long bb;
    PACK2(bb, f.x, f.y);
    FMA2(acc0[12], bb, xx0);
    FMA2(acc1[12], bb, xx1);
}

// softmax (no max-subtract; unit-norm rows, x~N(0,1)) + packed writeback
__device__ __forceinline__ void softmax_store(const unsigned long long* acc,
                                              unsigned long long* w) {
    float e[ALPHA];
    #pragma unroll
    for (int p = 0; p < 13; ++p) {
        float a, b;
        UNPACK2(a, b, acc[p]);
        e[2*p] = __expf(a); e[2*p+1] = __expf(b);
    }
    float t[13];
    #pragma unroll
    for (int p = 0; p < 13; ++p) t[p] = e[2*p] + e[2*p+1];
    float sa = (t[0] + t[1]) + (t[2] + t[3]);
    float sb = (t[4] + t[5]) + (t[6] + t[7]);
    float sc = (t[8] + t[9]) + (t[10] + t[11]);
    float sm = (sa + sb) + (sc + t[12]);
    float inv = __fdividef(1.0f, sm);
    unsigned long long iv;
    PACK_DUP(iv, inv);
    #pragma unroll
    for (int p = 0; p < 13; ++p) {
        unsigned long long pk, r;
        PACK2(pk, e[2*p], e[2*p+1]);
        MUL2(r, pk, iv);
        w[p] = r;
    }
}

// ============================================================
// TMA tensor-map kernel: warp handles 64 batches at ONE s (uniform shift)
// ============================================================
__global__ __launch_bounds__(TPB, 2)
void rotor_tma_kernel(const __grid_constant__ CUtensorMap mx,
                      const __grid_constant__ CUtensorMap mo,
                      const float* __restrict__ rotor, int nChunks)
{
    extern __shared__ __align__(128) float s_dyn[];
    __shared__ __align__(16) float s_rn[ALPHA][ALPHA + 2];
    __shared__ float s_inv[ALPHA];
    __shared__ __align__(8) unsigned long long s_mbar[WARPS * 2];

    const int tid  = threadIdx.x;
    const int wid  = tid >> 5;
    const int lane = tid & 31;

    if (tid < ALPHA) {
        float ss = 0.f;
        #pragma unroll
        for (int j = 0; j < ALPHA; ++j) {
            float v = rotor[tid * ALPHA + j];
            ss = fmaf(v, v, ss);
        }
        s_inv[tid] = rsqrtf(ss);
    }
    if (tid < WARPS * 2) mbar_init(smem_u32(&s_mbar[tid]), 1);
    __syncthreads();
    for (int e = tid; e < ALPHA * ALPHA; e += TPB) {
        int r = e / ALPHA;
        s_rn[r][e - r * ALPHA] = rotor[e] * s_inv[r];
    }
    __syncthreads();

    float* __restrict__ wbuf = s_dyn + wid * 2 * CHUNK_FLOATS;
    const uint32_t wb  = smem_u32(wbuf);
    const uint32_t mbA = smem_u32(&s_mbar[wid * 2 + 0]);
    const uint32_t mbB = smem_u32(&s_mbar[wid * 2 + 1]);
    const char* rn_base = (const char*)&s_rn[0][0];

    const int c0 = blockIdx.x * WARPS + wid;

    // chunk c -> s = c & 8191, batch group b0 = 64*(c>>13)
    if (lane == 0) {
        if (c0 < nChunks) {
            mbar_expect_tx(mbA, CHUNK_BYTES);
            tmap_load_2d(wb, &mx, (c0 & (SEQ-1)) * ALPHA, (c0 >> 13) << 6, mbA);
        }
        int c1 = c0 + TW;
        if (c1 < nChunks) {
            mbar_expect_tx(mbB, CHUNK_BYTES);
            tmap_load_2d(wb + CHUNK_BYTES, &mx, (c1 & (SEQ-1)) * ALPHA, (c1 >> 13) << 6, mbB);
        }
    }

    int k = 0;
    for (int c = c0; c < nChunks; c += TW, ++k) {
        const int b  = k & 1;
        const int ph = (k >> 1) & 1;
        mbar_wait(b ? mbB : mbA, ph);

        float* __restrict__ sb = wbuf + b * CHUNK_FLOATS;
        const int s     = c & (SEQ - 1);
        const int bg    = (c >> 13) << 6;
        const int shift = s % ALPHA;                  // UNIFORM across warp

        const float* __restrict__ xr0 = sb + lane * ALPHA;         // batch bg+lane
        const float* __restrict__ xr1 = sb + (lane + 32) * ALPHA;  // batch bg+lane+32

        unsigned long long acc0[13], acc1[13];
        #pragma unroll
        for (int p = 0; p < 13; ++p) { acc0[p] = 0ull; acc1[p] = 0ull; }

        // i-loop: compile-time x offsets; rn row = (i+shift)%26, uniform incr+wrap
        uint32_t roff = (uint32_t)shift * 112u;
        #pragma unroll
        for (int q = 0; q < 13; ++q) {
            float2 xa = *(const float2*)(xr0 + 2 * q);   // x[2q], x[2q+1] (compile-time)
            float2 xb = *(const float2*)(xr1 + 2 * q);
            unsigned long long xx0, xx1;

            PACK_DUP(xx0, xa.x);
            PACK_DUP(xx1, xb.x);
            row_fma2(rn_base + roff, acc0, xx0, acc1, xx1);
            roff = (roff == 25u * 112u) ? 0u : roff + 112u;

            PACK_DUP(xx0, xa.y);
            PACK_DUP(xx1, xb.y);
            row_fma2(rn_base + roff, acc0, xx0, acc1, xx1);
            roff = (roff == 25u * 112u) ? 0u : roff + 112u;
        }

        softmax_store(acc0, (unsigned long long*)(sb + lane * ALPHA));
        softmax_store(acc1, (unsigned long long*)(sb + (lane + 32) * ALPHA));
        __syncwarp();

        if (lane == 0) {
            fence_async();
            tmap_store_2d(&mo, s * ALPHA, bg, wb + b * CHUNK_BYTES);
            bulk_commit();
            const int cn = c + 2 * TW;
            if (cn < nChunks) {
                bulk_wait_read();
                mbar_expect_tx(b ? mbB : mbA, CHUNK_BYTES);
                tmap_load_2d(wb + b * CHUNK_BYTES, &mx,
                             (cn & (SEQ-1)) * ALPHA, (cn >> 13) << 6, b ? mbB : mbA);
            }
        }
    }
    if (lane == 0) bulk_wait_all();
}

// ============================================================
// Fallback kernel (R13): consecutive tokens, per-lane shifts, 1D bulk
// ============================================================
__global__ __launch_bounds__(TPB, 2)
void rotor_kernel(const float* __restrict__ x,
                  const float* __restrict__ rotor,
                  float* __restrict__ out, int nChunks)
{
    extern __shared__ __align__(128) float s_dyn[];
    __shared__ __align__(16) float s_rn[ALPHA][ALPHA + 2];
    __shared__ float s_inv[ALPHA];
    __shared__ __align__(8) unsigned long long s_mbar[WARPS * 2];

    const int tid  = threadIdx.x;
    const int wid  = tid >> 5;
    const int lane = tid & 31;

    if (tid < ALPHA) {
        float ss = 0.f;
        #pragma unroll
        for (int j = 0; j < ALPHA; ++j) {
            float v = rotor[tid * ALPHA + j];
            ss = fmaf(v, v, ss);
        }
        s_inv[tid] = rsqrtf(ss);
    }
    if (tid < WARPS * 2) mbar_init(smem_u32(&s_mbar[tid]), 1);
    __syncthreads();
    for (int e = tid; e < ALPHA * ALPHA; e += TPB) {
        int r = e / ALPHA;
        s_rn[r][e - r * ALPHA] = rotor[e] * s_inv[r];
    }
    __syncthreads();

    float* __restrict__ wbuf = s_dyn + wid * 2 * CHUNK_FLOATS;
    const uint32_t wb  = smem_u32(wbuf);
    const uint32_t mbA = smem_u32(&s_mbar[wid * 2 + 0]);
    const uint32_t mbB = smem_u32(&s_mbar[wid * 2 + 1]);
    const char* rn_base = (const char*)&s_rn[0][0];

    const int c0 = blockIdx.x * WARPS + wid;

    if (lane == 0) {
        if (c0 < nChunks) {
            mbar_expect_tx(mbA, CHUNK_BYTES);
            bulk_load(wb, x + (size_t)c0 * CHUNK_FLOATS, CHUNK_BYTES, mbA);
        }
        if (c0 + TW < nChunks) {
            mbar_expect_tx(mbB, CHUNK_BYTES);
            bulk_load(wb + CHUNK_BYTES, x + (size_t)(c0 + TW) * CHUNK_FLOATS,
                      CHUNK_BYTES, mbB);
        }
    }

    int k = 0;
    for (int c = c0; c < nChunks; c += TW, ++k) {
        const int b  = k & 1;
        const int ph = (k >> 1) & 1;
        mbar_wait(b ? mbB : mbA, ph);

        float* __restrict__ sb = wbuf + b * CHUNK_FLOATS;
        const int tok0 = c * CHUNK_TOK + lane;
        const int tok1 = tok0 + 32;
        const int shift0 = (tok0 & (SEQ - 1)) % ALPHA;
        const int shift1 = (tok1 & (SEQ - 1)) % ALPHA;
        const float* __restrict__ xr0 = sb + lane * ALPHA;
        const float* __restrict__ xr1 = sb + (lane + 32) * ALPHA;

        unsigned long long acc0[13], acc1[13];
        #pragma unroll
        for (int p = 0; p < 13; ++p) { acc0[p] = 0ull; acc1[p] = 0ull; }

        #pragma unroll
        for (int r = 0; r < ALPHA; ++r) {
            int i0 = r - shift0; i0 += (i0 >> 31) & ALPHA;
            int i1 = r - shift1; i1 += (i1 >> 31) & ALPHA;
            unsigned long long xx0, xx1;
            PACK_DUP(xx0, xr0[i0]);
            PACK_DUP(xx1, xr1[i1]);
            row_fma2(rn_base + r * 112, acc0, xx0, acc1, xx1);
        }

        softmax_store(acc0, (unsigned long long*)(sb + lane * ALPHA));
        softmax_store(acc1, (unsigned long long*)(sb + (lane + 32) * ALPHA));
        __syncwarp();

        if (lane == 0) {
            fence_async();
            bulk_store(out + (size_t)c * CHUNK_FLOATS, wb + b * CHUNK_BYTES, CHUNK_BYTES);
            bulk_commit();
            const int cn = c + 2 * TW;
            if (cn < nChunks) {
                bulk_wait_read();
                mbar_expect_tx(b ? mbB : mbA, CHUNK_BYTES);
                bulk_load(wb + b * CHUNK_BYTES, x + (size_t)cn * CHUNK_FLOATS,
                          CHUNK_BYTES, b ? mbB : mbA);
            }
        }
    }
    if (lane == 0) bulk_wait_all();
}

// ============================================================
// Host
// ============================================================
typedef CUresult (*EncodeFn)(CUtensorMap*, CUtensorMapDataType, cuuint32_t, void*,
                             const cuuint64_t*, const cuuint64_t*,
                             const cuuint32_t*, const cuuint32_t*,
                             CUtensorMapInterleave, CUtensorMapSwizzle,
                             CUtensorMapL2promotion, CUtensorMapFloatOOBfill);

static bool encode_map(EncodeFn fn, CUtensorMap* m, void* base) {
    cuuint64_t dims[2]    = { (cuuint64_t)SEQ * ALPHA, (cuuint64_t)NBATCH };
    cuuint64_t strides[1] = { (cuuint64_t)SEQ * ALPHA * 4 };   // 851968, 16B multiple
    cuuint32_t box[2]     = { ALPHA, 64 };
    cuuint32_t estr[2]    = { 1, 1 };
    CUresult r = fn(m, CU_TENSOR_MAP_DATA_TYPE_FLOAT32, 2, base,
                    dims, strides, box, estr,
                    CU_TENSOR_MAP_INTERLEAVE_NONE, CU_TENSOR_MAP_SWIZZLE_NONE,
                    CU_TENSOR_MAP_L2_PROMOTION_L2_128B,
                    CU_TENSOR_MAP_FLOAT_OOB_FILL_NONE);
    return r == CUDA_SUCCESS;
}

extern "C" void kernel_launch(void* const* d_in, const int* in_sizes, int n_in,
                              void* d_out, int out_size)
{
    const float* x     = (const float*)d_in[0];
    const float* rotor = (const float*)d_in[1];
    float* out         = (float*)d_out;

    const int total_tokens = out_size / ALPHA;    // 1,048,576
    const int nChunks = total_tokens / CHUNK_TOK; // 16384
    const int dyn_smem = WARPS * 2 * CHUNK_BYTES; // 106496 B

    // Try to build tensor maps via driver API loaded at runtime (no -lcuda link).
    bool tma_ok = false;
    CUtensorMap mx, mo;
    void* h = dlopen("libcuda.so.1", RTLD_LAZY | RTLD_GLOBAL);
    if (!h) h = dlopen("libcuda.so", RTLD_LAZY | RTLD_GLOBAL);
    if (h) {
        EncodeFn fn = (EncodeFn)dlsym(h, "cuTensorMapEncodeTiled");
        if (fn)
            tma_ok = encode_map(fn, &mx, (void*)x) && encode_map(fn, &mo, (void*)out);
    }

    if (tma_ok) {
        cudaFuncSetAttribute(rotor_tma_kernel,
                             cudaFuncAttributeMaxDynamicSharedMemorySize, dyn_smem);
        rotor_tma_kernel<<<GRID, TPB, dyn_smem>>>(mx, mo, rotor, nChunks);
    } else {
        cudaFuncSetAttribute(rotor_kernel,
                             cudaFuncAttributeMaxDynamicSharedMemorySize, dyn_smem);
        rotor_kernel<<<GRID, TPB, dyn_smem>>>(x, rotor, out, nChunks);
    }
}